// round 3
// baseline (speedup 1.0000x reference)
#include <cuda_runtime.h>
#include <cstdint>

// B=8, C=16, H=512, W=512, M=N=15
//   K:     [128, 16, 16]  f32
//   basis: [262144, 16, 16] f32, separable: basis[h*W+w,p,q] = Bu[h,p]*Bv[w,q]
//   out:   [128, 512, 512] f32
//
// Bu[h,p] = sum_q basis[h*W, p, q]; Bv[w,q] = sum_p basis[w, p, q]
// out[bc,h,w] = sum_p Bu[h,p] * T[p,w],  T[p,w] = sum_q K[bc,p,q]*Bv[w,q]

#define HH 512
#define WW 512
#define PP 16
#define QQ 16
#define BC 128
#define TILE 128   // 128h x 128w per block, 8x8 per thread

__device__ float g_Bu[HH * PP];   // 32 KB (h-major)
__device__ float g_Bv[WW * QQ];   // 32 KB (w-major)

// ---------------------------------------------------------------------------
// Kernel A: extract Bu, Bv via partition-of-unity sums.
// ---------------------------------------------------------------------------
__global__ __launch_bounds__(256) void extract_factors(const float* __restrict__ basis) {
    int tid = threadIdx.x;
    if (blockIdx.x < 64) {
        int warp = tid >> 5, lane = tid & 31;
        int h = blockIdx.x * 8 + warp;
        const float4* r4 = reinterpret_cast<const float4*>(basis + (size_t)h * WW * (PP * QQ));
        float4 a = r4[lane * 2];
        float4 b = r4[lane * 2 + 1];
        float s = (a.x + a.y) + (a.z + a.w) + (b.x + b.y) + (b.z + b.w);
        s += __shfl_xor_sync(0xffffffffu, s, 1);
        if ((lane & 1) == 0) g_Bu[h * PP + (lane >> 1)] = s;
    } else {
        __shared__ float sb[16 * PP * QQ];
        int w0 = (blockIdx.x - 64) * 16;
        const float4* src = reinterpret_cast<const float4*>(basis + (size_t)w0 * (PP * QQ));
        float4* dst = reinterpret_cast<float4*>(sb);
        #pragma unroll
        for (int i = tid; i < 16 * PP * QQ / 4; i += 256) dst[i] = src[i];
        __syncthreads();
        int wl = tid >> 4, q = tid & 15;
        float s = 0.f;
        #pragma unroll
        for (int p = 0; p < PP; ++p) s += sb[wl * (PP * QQ) + p * QQ + q];
        g_Bv[(w0 + wl) * QQ + q] = s;
    }
}

// ---------------------------------------------------------------------------
// Kernel B (fused, register-tiled):
//   grid = (W/TILE, H/TILE, BC), 256 threads.
//   thread t: tw = t&15 (8 w cols), th = t>>4 (8 h rows) -> 8x8 output tile.
//   Prologue: stage K, Bv tile; compute sT[p][w]; stage duplicated Bu pairs.
//   Main: 16 p-steps, each 6 LDS.128 + 32 FFMA2, 32 independent chains.
// ---------------------------------------------------------------------------
__global__ __launch_bounds__(256, 2) void fused_stage(const float* __restrict__ K,
                                                      float* __restrict__ out) {
    int bc = blockIdx.z;
    int h0 = blockIdx.y * TILE;
    int w0 = blockIdx.x * TILE;
    int t = threadIdx.x;
    int tw = t & 15;        // w-tile: w = w0 + tw*8 .. +7
    int th = t >> 4;        // h-tile: h = h0 + th*8 .. +7

    __shared__ float sK[PP * QQ];                       // 1 KB
    __shared__ float sBv[TILE * QQ];                    // 8 KB
    __shared__ float sT[PP][TILE];                      // 8 KB
    __shared__ unsigned long long sBu2[PP][TILE];       // 16 KB (dup'd pairs, p-major)

    // Stage K[bc] (256 floats)
    sK[t] = K[(size_t)bc * (PP * QQ) + t];

    // Stage Bv tile for w in [w0, w0+128): 2048 floats
    {
        const float4* src = reinterpret_cast<const float4*>(g_Bv + (size_t)w0 * QQ);
        float4* dst = reinterpret_cast<float4*>(sBv);
        #pragma unroll
        for (int i = t; i < TILE * QQ / 4; i += 256) dst[i] = src[i];
    }

    // Stage duplicated Bu: sBu2[p][hh] = (b,b), b = g_Bu[(h0+hh)*16 + p]
    #pragma unroll
    for (int i = t; i < PP * TILE; i += 256) {
        int p = i >> 7, hh = i & 127;
        float b = g_Bu[(size_t)(h0 + hh) * PP + p];
        unsigned long long bb;
        asm("mov.b64 %0, {%1, %2};" : "=l"(bb) : "f"(b), "f"(b));
        sBu2[p][hh] = bb;
    }
    __syncthreads();

    // Compute sT[p][w] = sum_q K[p][q] * Bv[w][q]
    #pragma unroll
    for (int i = t; i < PP * TILE; i += 256) {
        int p = i >> 7, ww = i & 127;
        float s = 0.f;
        #pragma unroll
        for (int q = 0; q < QQ; ++q) s = fmaf(sK[p * QQ + q], sBv[ww * QQ + q], s);
        sT[p][ww] = s;
    }
    __syncthreads();

    // Main loop: 8x8 register tile, accumulators as f32x2 pairs over w
    unsigned long long acc[8][4];
    #pragma unroll
    for (int i = 0; i < 8; ++i)
        #pragma unroll
        for (int j = 0; j < 4; ++j) acc[i][j] = 0ull;

    #pragma unroll
    for (int p = 0; p < PP; ++p) {
        // 8 dup'd Bu values for our h rows (4 x LDS.128)
        unsigned long long bu[8];
        {
            const ulonglong2* bp = reinterpret_cast<const ulonglong2*>(&sBu2[p][th * 8]);
            #pragma unroll
            for (int j = 0; j < 4; ++j) {
                ulonglong2 v = bp[j];
                bu[2 * j] = v.x;
                bu[2 * j + 1] = v.y;
            }
        }
        // 8 T values for our w cols as 4 f32x2 pairs (2 x LDS.128)
        unsigned long long tv[4];
        {
            const ulonglong2* tp = reinterpret_cast<const ulonglong2*>(&sT[p][tw * 8]);
            ulonglong2 a = tp[0], b = tp[1];
            tv[0] = a.x; tv[1] = a.y; tv[2] = b.x; tv[3] = b.y;
        }
        #pragma unroll
        for (int i = 0; i < 8; ++i)
            #pragma unroll
            for (int j = 0; j < 4; ++j)
                asm("fma.rn.f32x2 %0, %1, %2, %0;" : "+l"(acc[i][j]) : "l"(bu[i]), "l"(tv[j]));
    }

    // Store 8 rows x 8 cols (2 x STG.128 per row), streaming
    float* obase = out + (size_t)bc * HH * WW + (size_t)(h0 + th * 8) * WW + w0 + tw * 8;
    #pragma unroll
    for (int i = 0; i < 8; ++i) {
        float4* o = reinterpret_cast<float4*>(obase + (size_t)i * WW);
        float x0, y0, x1, y1, x2, y2, x3, y3;
        asm("mov.b64 {%0, %1}, %2;" : "=f"(x0), "=f"(y0) : "l"(acc[i][0]));
        asm("mov.b64 {%0, %1}, %2;" : "=f"(x1), "=f"(y1) : "l"(acc[i][1]));
        asm("mov.b64 {%0, %1}, %2;" : "=f"(x2), "=f"(y2) : "l"(acc[i][2]));
        asm("mov.b64 {%0, %1}, %2;" : "=f"(x3), "=f"(y3) : "l"(acc[i][3]));
        __stcs(o, make_float4(x0, y0, x1, y1));
        __stcs(o + 1, make_float4(x2, y2, x3, y3));
    }
}

// ---------------------------------------------------------------------------
extern "C" void kernel_launch(void* const* d_in, const int* in_sizes, int n_in,
                              void* d_out, int out_size) {
    const float* K     = (const float*)d_in[0];
    const float* basis = (const float*)d_in[1];
    float* out = (float*)d_out;
    (void)in_sizes; (void)n_in; (void)out_size;

    extract_factors<<<96, 256>>>(basis);

    dim3 grid(WW / TILE, HH / TILE, BC);
    fused_stage<<<grid, 256>>>(K, out);
}

// round 4
// speedup vs baseline: 1.5928x; 1.5928x over previous
#include <cuda_runtime.h>
#include <cstdint>

// B=8, C=16, H=512, W=512, M=N=15
//   K:     [128, 16, 16]  f32
//   basis: [262144, 16, 16] f32, separable: basis[h*W+w,p,q] = Bu[h,p]*Bv[w,q]
//   out:   [128, 512, 512] f32
//
// Bu[h,p] = sum_q basis[h*W, p, q]; Bv[w,q] = sum_p basis[w, p, q]
// out[bc,h,w] = sum_p Bu[h,p] * T[p,w],  T[p,w] = sum_q K[bc,p,q]*Bv[w,q]

#define HH 512
#define WW 512
#define PP 16
#define QQ 16
#define BC 128
#define ROWS 64

// Bu stored transposed + duplicated: g_Bu2[p*512 + h] = (Bu[h,p], Bu[h,p])
__device__ unsigned long long g_Bu2[PP * HH];   // 64 KB
__device__ float g_Bv[WW * QQ];                 // 32 KB (w-major)

__device__ __forceinline__ unsigned long long pk(float a, float b) {
    unsigned long long r;
    asm("mov.b64 %0, {%1, %2};" : "=l"(r) : "f"(a), "f"(b));
    return r;
}
__device__ __forceinline__ void fma2(unsigned long long& d, unsigned long long a,
                                     unsigned long long b) {
    asm("fma.rn.f32x2 %0, %1, %2, %0;" : "+l"(d) : "l"(a), "l"(b));
}
__device__ __forceinline__ void unpk(unsigned long long v, float& a, float& b) {
    asm("mov.b64 {%0, %1}, %2;" : "=f"(a), "=f"(b) : "l"(v));
}

// ---------------------------------------------------------------------------
// Kernel A: extract Bu (dup'd, p-major) and Bv via partition-of-unity sums.
// ---------------------------------------------------------------------------
__global__ __launch_bounds__(256) void extract_factors(const float* __restrict__ basis) {
    int tid = threadIdx.x;
    if (blockIdx.x < 64) {
        int warp = tid >> 5, lane = tid & 31;
        int h = blockIdx.x * 8 + warp;
        const float4* r4 = reinterpret_cast<const float4*>(basis + (size_t)h * WW * (PP * QQ));
        float4 a = r4[lane * 2];
        float4 b = r4[lane * 2 + 1];
        float s = (a.x + a.y) + (a.z + a.w) + (b.x + b.y) + (b.z + b.w);
        s += __shfl_xor_sync(0xffffffffu, s, 1);
        if ((lane & 1) == 0) {
            int p = lane >> 1;
            g_Bu2[p * HH + h] = pk(s, s);
        }
    } else {
        __shared__ float sb[16 * PP * QQ];
        int w0 = (blockIdx.x - 64) * 16;
        const float4* src = reinterpret_cast<const float4*>(basis + (size_t)w0 * (PP * QQ));
        float4* dst = reinterpret_cast<float4*>(sb);
        #pragma unroll
        for (int i = tid; i < 16 * PP * QQ / 4; i += 256) dst[i] = src[i];
        __syncthreads();
        int wl = tid >> 4, q = tid & 15;
        float s = 0.f;
        #pragma unroll
        for (int p = 0; p < PP; ++p) s += sb[wl * (PP * QQ) + p * QQ + q];
        g_Bv[(w0 + wl) * QQ + q] = s;
    }
}

// ---------------------------------------------------------------------------
// Kernel B (fused): grid = (H/ROWS, BC), 128 threads.
//   Thread t owns w = 4t..4t+3. T held in 32 packed f32x2 registers.
//   Prologue: T[p] += (k,k) * (Bv pair) via packed FMA; K dup'd in smem.
//   Main loop: 4 h-rows per step -> 8 chains; bu via broadcast LDS.128.
// ---------------------------------------------------------------------------
__global__ __launch_bounds__(128) void fused_stage(const float* __restrict__ K,
                                                   float* __restrict__ out) {
    int bc = blockIdx.y;
    int h0 = blockIdx.x * ROWS;
    int t = threadIdx.x;

    __shared__ unsigned long long sK2[PP * QQ];    // (k,k) pairs, 2 KB
    __shared__ unsigned long long sBu2[PP * ROWS]; // (b,b) pairs, 8 KB

    // Stage K[bc] duplicated
    {
        float k0 = K[(size_t)bc * (PP * QQ) + t];
        float k1 = K[(size_t)bc * (PP * QQ) + t + 128];
        sK2[t] = pk(k0, k0);
        sK2[t + 128] = pk(k1, k1);
    }
    // Stage Bu tile: coalesced u64 copy (p-major chunks of 64)
    #pragma unroll
    for (int i = t; i < PP * ROWS; i += 128) {
        int p = i >> 6, hh = i & 63;
        sBu2[i] = g_Bu2[p * HH + h0 + hh];
    }
    __syncthreads();

    // Prologue: Txy[p]=(T[p][w0],T[p][w1]), Tzw[p]=(T[p][w2],T[p][w3])
    unsigned long long Txy[PP], Tzw[PP];
    #pragma unroll
    for (int p = 0; p < PP; ++p) { Txy[p] = 0ull; Tzw[p] = 0ull; }

    const float4* bv4 = reinterpret_cast<const float4*>(g_Bv);
    #pragma unroll
    for (int j = 0; j < 4; ++j) {       // q-groups of 4
        float4 v0 = bv4[(4 * t + 0) * 4 + j];
        float4 v1 = bv4[(4 * t + 1) * 4 + j];
        float4 v2 = bv4[(4 * t + 2) * 4 + j];
        float4 v3 = bv4[(4 * t + 3) * 4 + j];
        unsigned long long a01[4], a23[4];
        a01[0] = pk(v0.x, v1.x); a23[0] = pk(v2.x, v3.x);
        a01[1] = pk(v0.y, v1.y); a23[1] = pk(v2.y, v3.y);
        a01[2] = pk(v0.z, v1.z); a23[2] = pk(v2.z, v3.z);
        a01[3] = pk(v0.w, v1.w); a23[3] = pk(v2.w, v3.w);
        #pragma unroll
        for (int p = 0; p < PP; ++p) {
            #pragma unroll
            for (int qq = 0; qq < 4; ++qq) {
                unsigned long long kk = sK2[p * QQ + j * 4 + qq];  // broadcast
                fma2(Txy[p], kk, a01[qq]);
                fma2(Tzw[p], kk, a23[qq]);
            }
        }
    }

    float* obase = out + (size_t)bc * HH * WW + (size_t)h0 * WW + 4 * t;

    // Main loop: 4 rows per step, 8 independent FFMA2 chains
    #pragma unroll 2
    for (int g = 0; g < ROWS; g += 4) {
        unsigned long long acc[4][2];
        #pragma unroll
        for (int i = 0; i < 4; ++i) { acc[i][0] = 0ull; acc[i][1] = 0ull; }

        #pragma unroll
        for (int p = 0; p < PP; ++p) {
            // 4 dup'd Bu values, warp-uniform broadcast (2 x LDS.128)
            const ulonglong2* bp = reinterpret_cast<const ulonglong2*>(&sBu2[p * ROWS + g]);
            ulonglong2 b01 = bp[0];
            ulonglong2 b23 = bp[1];
            fma2(acc[0][0], b01.x, Txy[p]); fma2(acc[0][1], b01.x, Tzw[p]);
            fma2(acc[1][0], b01.y, Txy[p]); fma2(acc[1][1], b01.y, Tzw[p]);
            fma2(acc[2][0], b23.x, Txy[p]); fma2(acc[2][1], b23.x, Tzw[p]);
            fma2(acc[3][0], b23.y, Txy[p]); fma2(acc[3][1], b23.y, Tzw[p]);
        }

        #pragma unroll
        for (int i = 0; i < 4; ++i) {
            float x, y, z, w;
            unpk(acc[i][0], x, y);
            unpk(acc[i][1], z, w);
            *reinterpret_cast<float4*>(obase + (size_t)(g + i) * WW) = make_float4(x, y, z, w);
        }
    }
}

// ---------------------------------------------------------------------------
extern "C" void kernel_launch(void* const* d_in, const int* in_sizes, int n_in,
                              void* d_out, int out_size) {
    const float* K     = (const float*)d_in[0];
    const float* basis = (const float*)d_in[1];
    float* out = (float*)d_out;
    (void)in_sizes; (void)n_in; (void)out_size;

    extract_factors<<<96, 256>>>(basis);

    dim3 grid(HH / ROWS, BC);
    fused_stage<<<grid, 128>>>(K, out);
}

// round 5
// speedup vs baseline: 2.3103x; 1.4505x over previous
#include <cuda_runtime.h>
#include <cstdint>

// B=8, C=16, H=512, W=512, M=N=15
//   K:     [128, 16, 16]  f32
//   basis: [262144, 16, 16] f32, separable: basis[h*W+w,p,q] = Bu[h,p]*Bv[w,q]
//   out:   [128, 512, 512] f32
//
// Bu[h,p] = sum_q basis[h*W, p, q]; Bv[w,q] = sum_p basis[w, p, q]
// T[bc,p,w] = sum_q K[bc,p,q]*Bv[w,q];  out[bc,h,w] = sum_p Bu[h,p]*T[bc,p,w]

#define HH 512
#define WW 512
#define PP 16
#define QQ 16
#define BC 128
#define ROWS 64

__device__ float g_But[PP * HH];        // Bu transposed: [p][h], 32 KB
__device__ float g_BvT[QQ * WW];        // Bv transposed: [q][w], 32 KB
__device__ float g_T[BC * PP * WW];     // T scratch: [bc][p][w], 16 MB

__device__ __forceinline__ unsigned long long pk(float a, float b) {
    unsigned long long r;
    asm("mov.b64 %0, {%1, %2};" : "=l"(r) : "f"(a), "f"(b));
    return r;
}
__device__ __forceinline__ void fma2(unsigned long long& d, unsigned long long a,
                                     unsigned long long b) {
    asm("fma.rn.f32x2 %0, %1, %2, %0;" : "+l"(d) : "l"(a), "l"(b));
}
__device__ __forceinline__ void unpk(unsigned long long v, float& a, float& b) {
    asm("mov.b64 {%0, %1}, %2;" : "=f"(a), "=f"(b) : "l"(v));
}

// ---------------------------------------------------------------------------
// Kernel A: extract factors. Warp-per-row, coalesced loads, shfl reductions.
//   blocks 0..63  : Bu rows (h = 8*blk + warp)
//   blocks 64..127: Bv rows (w = 8*(blk-64) + warp)
// ---------------------------------------------------------------------------
__global__ __launch_bounds__(256) void extract_factors(const float* __restrict__ basis) {
    int warp = threadIdx.x >> 5, lane = threadIdx.x & 31;
    if (blockIdx.x < 64) {
        int h = blockIdx.x * 8 + warp;
        const float4* r4 = reinterpret_cast<const float4*>(basis + (size_t)h * WW * (PP * QQ));
        float4 a = r4[lane * 2];
        float4 b = r4[lane * 2 + 1];
        float s = (a.x + a.y) + (a.z + a.w) + (b.x + b.y) + (b.z + b.w);
        s += __shfl_xor_sync(0xffffffffu, s, 1);   // lanes (2k,2k+1) cover p=k
        if ((lane & 1) == 0) g_But[(lane >> 1) * HH + h] = s;
    } else {
        int w = (blockIdx.x - 64) * 8 + warp;
        const float4* r4 = reinterpret_cast<const float4*>(basis + (size_t)w * (PP * QQ));
        float4 a = r4[lane * 2];
        float4 b = r4[lane * 2 + 1];
        // lane l holds p = l>>1, q = (l&1)*8 + j. Reduce over p: butterfly
        // across lanes of equal parity (offsets 2,4,8,16), per component.
        #pragma unroll
        for (int off = 2; off <= 16; off <<= 1) {
            a.x += __shfl_xor_sync(0xffffffffu, a.x, off);
            a.y += __shfl_xor_sync(0xffffffffu, a.y, off);
            a.z += __shfl_xor_sync(0xffffffffu, a.z, off);
            a.w += __shfl_xor_sync(0xffffffffu, a.w, off);
            b.x += __shfl_xor_sync(0xffffffffu, b.x, off);
            b.y += __shfl_xor_sync(0xffffffffu, b.y, off);
            b.z += __shfl_xor_sync(0xffffffffu, b.z, off);
            b.w += __shfl_xor_sync(0xffffffffu, b.w, off);
        }
        if (lane < 2) {
            int q0 = lane * 8;   // lane0: q=0..7, lane1: q=8..15
            g_BvT[(q0 + 0) * WW + w] = a.x;
            g_BvT[(q0 + 1) * WW + w] = a.y;
            g_BvT[(q0 + 2) * WW + w] = a.z;
            g_BvT[(q0 + 3) * WW + w] = a.w;
            g_BvT[(q0 + 4) * WW + w] = b.x;
            g_BvT[(q0 + 5) * WW + w] = b.y;
            g_BvT[(q0 + 6) * WW + w] = b.z;
            g_BvT[(q0 + 7) * WW + w] = b.w;
        }
    }
}

// ---------------------------------------------------------------------------
// Kernel B: T[bc,p,w] = sum_q K[bc,p,q] * Bv[w,q]
//   grid (2, BC), 256 threads; thread owns one w, all 16 p.
// ---------------------------------------------------------------------------
__global__ __launch_bounds__(256) void stage1(const float* __restrict__ K) {
    int bc = blockIdx.y;
    int w = blockIdx.x * 256 + threadIdx.x;

    __shared__ float sK[PP * QQ];
    sK[threadIdx.x] = K[(size_t)bc * (PP * QQ) + threadIdx.x];

    float rv[QQ];
    #pragma unroll
    for (int q = 0; q < QQ; ++q) rv[q] = g_BvT[q * WW + w];
    __syncthreads();

    float* tb = g_T + (size_t)bc * PP * WW + w;
    #pragma unroll
    for (int p = 0; p < PP; ++p) {
        float s = 0.f;
        #pragma unroll
        for (int q = 0; q < QQ; ++q) s = fmaf(sK[p * QQ + q], rv[q], s);
        tb[p * WW] = s;
    }
}

// ---------------------------------------------------------------------------
// Kernel C: out[bc,h,w] = sum_p Bu[h,p] * T[bc,p,w]
//   grid (H/ROWS, BC), 128 threads; thread t owns w = 4t..4t+3.
//   Accumulator pairs packed over h: acc[w][hp] = (out[h0,w], out[h1,w]).
//   Bu operand = natural pair from one broadcast LDS.128 (no duplication).
//   T dup'd once into 64 u64 registers in the prologue.
// ---------------------------------------------------------------------------
__global__ __launch_bounds__(128) void fused_stage(float* __restrict__ out) {
    int bc = blockIdx.y;
    int h0 = blockIdx.x * ROWS;
    int t = threadIdx.x;

    __shared__ float sBu[PP * ROWS];   // [p][hh], 4 KB

    // Stage Bu tile (coalesced float4 copy)
    {
        const float4* src = reinterpret_cast<const float4*>(g_But);
        float4* dst = reinterpret_cast<float4*>(sBu);
        #pragma unroll
        for (int i = t; i < PP * ROWS / 4; i += 128) {
            int p = i >> 4, c = i & 15;
            dst[i] = src[(p * HH + h0) / 4 + c];
        }
    }

    // Load T[p][4t..4t+3] and duplicate into register pairs
    unsigned long long Td[PP][4];
    {
        const float4* t4 = reinterpret_cast<const float4*>(g_T + (size_t)bc * PP * WW);
        #pragma unroll
        for (int p = 0; p < PP; ++p) {
            float4 tl = t4[p * (WW / 4) + t];
            Td[p][0] = pk(tl.x, tl.x);
            Td[p][1] = pk(tl.y, tl.y);
            Td[p][2] = pk(tl.z, tl.z);
            Td[p][3] = pk(tl.w, tl.w);
        }
    }
    __syncthreads();

    float* obase = out + (size_t)bc * HH * WW + (size_t)h0 * WW + 4 * t;

    #pragma unroll 2
    for (int g = 0; g < ROWS; g += 4) {
        unsigned long long acc[4][2];
        #pragma unroll
        for (int w = 0; w < 4; ++w) { acc[w][0] = 0ull; acc[w][1] = 0ull; }

        #pragma unroll
        for (int p = 0; p < PP; ++p) {
            // Broadcast LDS.128: Bu for h = h0+g..h0+g+3, as 2 natural pairs
            ulonglong2 v = *reinterpret_cast<const ulonglong2*>(&sBu[p * ROWS + g]);
            fma2(acc[0][0], v.x, Td[p][0]);
            fma2(acc[1][0], v.x, Td[p][1]);
            fma2(acc[2][0], v.x, Td[p][2]);
            fma2(acc[3][0], v.x, Td[p][3]);
            fma2(acc[0][1], v.y, Td[p][0]);
            fma2(acc[1][1], v.y, Td[p][1]);
            fma2(acc[2][1], v.y, Td[p][2]);
            fma2(acc[3][1], v.y, Td[p][3]);
        }

        float r0[4], r1[4], r2[4], r3[4];
        #pragma unroll
        for (int w = 0; w < 4; ++w) {
            unpk(acc[w][0], r0[w], r1[w]);   // rows g, g+1
            unpk(acc[w][1], r2[w], r3[w]);   // rows g+2, g+3
        }
        *reinterpret_cast<float4*>(obase + (size_t)(g + 0) * WW) = make_float4(r0[0], r0[1], r0[2], r0[3]);
        *reinterpret_cast<float4*>(obase + (size_t)(g + 1) * WW) = make_float4(r1[0], r1[1], r1[2], r1[3]);
        *reinterpret_cast<float4*>(obase + (size_t)(g + 2) * WW) = make_float4(r2[0], r2[1], r2[2], r2[3]);
        *reinterpret_cast<float4*>(obase + (size_t)(g + 3) * WW) = make_float4(r3[0], r3[1], r3[2], r3[3]);
    }
}

// ---------------------------------------------------------------------------
extern "C" void kernel_launch(void* const* d_in, const int* in_sizes, int n_in,
                              void* d_out, int out_size) {
    const float* K     = (const float*)d_in[0];
    const float* basis = (const float*)d_in[1];
    float* out = (float*)d_out;
    (void)in_sizes; (void)n_in; (void)out_size;

    extract_factors<<<128, 256>>>(basis);

    dim3 g1(2, BC);
    stage1<<<g1, 256>>>(K);

    dim3 g2(HH / ROWS, BC);
    fused_stage<<<g2, 128>>>(out);
}